// round 5
// baseline (speedup 1.0000x reference)
#include <cuda_runtime.h>

// Problem constants
#define BATCH  32768
#define DD     16     // (lmax+1)^2
#define RR     64     // RANK
#define CO     64     // CH_OUT (== CH_IN1)
#define CI2    32     // CH_IN2

// Packed f32x2 helpers (Blackwell sm_103a dual-rate fp32 — only via PTX)
__device__ __forceinline__ unsigned long long pack2(float x) {
    unsigned long long r;
    asm("mov.b64 %0, {%1, %1};" : "=l"(r) : "f"(x));
    return r;
}
__device__ __forceinline__ unsigned long long fma2(unsigned long long a,
                                                   unsigned long long b,
                                                   unsigned long long c) {
    unsigned long long d;
    asm("fma.rn.f32x2 %0, %1, %2, %3;" : "=l"(d) : "l"(a), "l"(b), "l"(c));
    return d;
}
__device__ __forceinline__ unsigned long long mul2(unsigned long long a,
                                                   unsigned long long b) {
    unsigned long long d;
    asm("mul.rn.f32x2 %0, %1, %2;" : "=l"(d) : "l"(a), "l"(b));
    return d;
}
__device__ __forceinline__ float2 unpack2(unsigned long long v) {
    float2 f;
    asm("mov.b64 {%0, %1}, %2;" : "=f"(f.x), "=f"(f.y) : "l"(v));
    return f;
}

// out[b,c,o] = sum_r C[c,r] * t1[b,r,o] * t3[b,r,o]
//   t1[b,r,o] = sum_i x1[b,i,o] * A[i,r]
//   t2[b,r,v] = sum_j x2[b,j,v] * B[j,r]
//   t3[b,r,o] = sum_v t2[b,r,v] * w[b,o,v]
//
// One CTA per batch element, 256 threads = 8 warps.
// lane -> o-pair; warp g -> r-group of 8 (= 4 packed r-pairs).
// All r-indexed operands load as float4/ulonglong2 warp-uniform broadcasts
// (reinterpreted directly as f32x2 pairs); o-indexed operands are
// lane-contiguous float2. All FMA work is packed fma.rn.f32x2 over r-pairs.

__global__ __launch_bounds__(256, 2)
void cp_tp_kernel(const float* __restrict__ x1,
                  const float* __restrict__ x2,
                  const float* __restrict__ w,
                  const float* __restrict__ A,
                  const float* __restrict__ Bm,
                  const float* __restrict__ Cm,
                  float* __restrict__ out)
{
    const int b   = blockIdx.x;
    const int tid = threadIdx.x;

    __shared__ union {
        struct {
            float x1s[DD * CO];             // 1024  [i][o]
            float x2s[DD * CI2];            // 512   [i][v]
            float wT [CI2 * 66];            // 2112  [v][o]  stride 66
            float t2T[CI2 * 68];            // 2176  [v][r]  stride 68 (16B-aligned)
            float As [DD * RR];             // 1024  [i][r]
            float Bs [DD * RR];             // 1024  [i][r]
            unsigned long long CsP[32*18];  // [rpair][c] packed {C[c,2rp],C[c,2rp+1]}
        } s;
        float red[8 * DD * CO];             // 32 KB partial-sum buffer (aliased)
    } sm;

    // ---------------- fill shared memory ----------------
    {
        ((float4*)sm.s.x1s)[tid] = ((const float4*)(x1 + (size_t)b * DD * CO))[tid];
        if (tid < 128)
            ((float4*)sm.s.x2s)[tid] = ((const float4*)(x2 + (size_t)b * DD * CI2))[tid];
        ((float4*)sm.s.As)[tid] = ((const float4*)A)[tid];
        ((float4*)sm.s.Bs)[tid] = ((const float4*)Bm)[tid];
        // C packed into r-pairs: CsP[rp*18 + c] = {C[c][2rp], C[c][2rp+1]}
        #pragma unroll
        for (int k = 0; k < 2; k++) {
            int idx = tid + k * 256;          // 512 pairs total
            int rp = idx >> 4, c = idx & 15;
            sm.s.CsP[rp * 18 + c] = *(const unsigned long long*)&Cm[c * RR + 2 * rp];
        }
        // w[b][o][v] transpose into wT[v][o]
        const float* wg = w + (size_t)b * CO * CI2;
        #pragma unroll
        for (int k = 0; k < 8; k++) {
            int idx = tid + k * 256;
            int o = idx >> 5, v = idx & 31;
            sm.s.wT[v * 66 + o] = wg[idx];
        }
    }
    __syncthreads();

    const int lane = tid & 31;
    const int g    = tid >> 5;     // warp id = r-group
    const int r0   = g * 8;
    const int oo   = lane * 2;

    // ---------------- t2 phase: t2T[v][r0..r0+7], v = lane ----------------
    {
        unsigned long long acc2[4] = {0ull, 0ull, 0ull, 0ull};
        const int v = lane;
        #pragma unroll
        for (int i = 0; i < DD; i++) {
            unsigned long long xx = pack2(sm.s.x2s[i * CI2 + v]);       // lane-contiguous
            ulonglong2 b0 = *(const ulonglong2*)&sm.s.Bs[i * RR + r0];  // warp-uniform
            ulonglong2 b1 = *(const ulonglong2*)&sm.s.Bs[i * RR + r0 + 4];
            acc2[0] = fma2(xx, b0.x, acc2[0]);
            acc2[1] = fma2(xx, b0.y, acc2[1]);
            acc2[2] = fma2(xx, b1.x, acc2[2]);
            acc2[3] = fma2(xx, b1.y, acc2[3]);
        }
        *(ulonglong2*)&sm.s.t2T[v * 68 + r0]     = make_ulonglong2(acc2[0], acc2[1]);
        *(ulonglong2*)&sm.s.t2T[v * 68 + r0 + 4] = make_ulonglong2(acc2[2], acc2[3]);
    }
    __syncthreads();

    // ---------------- main: t1 and t3, packed over r-pairs ----------------
    unsigned long long t1a[2][4], t3a[2][4];
    #pragma unroll
    for (int k = 0; k < 4; k++) {
        t1a[0][k] = t1a[1][k] = 0ull;
        t3a[0][k] = t3a[1][k] = 0ull;
    }

    #pragma unroll
    for (int i = 0; i < DD; i++) {
        float2 xv = *(const float2*)&sm.s.x1s[i * CO + oo];             // lane-contiguous
        unsigned long long x0 = pack2(xv.x), x1p = pack2(xv.y);
        ulonglong2 a0 = *(const ulonglong2*)&sm.s.As[i * RR + r0];      // warp-uniform
        ulonglong2 a1 = *(const ulonglong2*)&sm.s.As[i * RR + r0 + 4];
        t1a[0][0] = fma2(a0.x, x0, t1a[0][0]);  t1a[1][0] = fma2(a0.x, x1p, t1a[1][0]);
        t1a[0][1] = fma2(a0.y, x0, t1a[0][1]);  t1a[1][1] = fma2(a0.y, x1p, t1a[1][1]);
        t1a[0][2] = fma2(a1.x, x0, t1a[0][2]);  t1a[1][2] = fma2(a1.x, x1p, t1a[1][2]);
        t1a[0][3] = fma2(a1.y, x0, t1a[0][3]);  t1a[1][3] = fma2(a1.y, x1p, t1a[1][3]);
    }

    #pragma unroll
    for (int v = 0; v < CI2; v++) {
        float2 wv = *(const float2*)&sm.s.wT[v * 66 + oo];              // lane-contiguous
        unsigned long long w0 = pack2(wv.x), w1 = pack2(wv.y);
        ulonglong2 t0 = *(const ulonglong2*)&sm.s.t2T[v * 68 + r0];     // warp-uniform
        ulonglong2 t1v = *(const ulonglong2*)&sm.s.t2T[v * 68 + r0 + 4];
        t3a[0][0] = fma2(t0.x, w0, t3a[0][0]);  t3a[1][0] = fma2(t0.x, w1, t3a[1][0]);
        t3a[0][1] = fma2(t0.y, w0, t3a[0][1]);  t3a[1][1] = fma2(t0.y, w1, t3a[1][1]);
        t3a[0][2] = fma2(t1v.x, w0, t3a[0][2]); t3a[1][2] = fma2(t1v.x, w1, t3a[1][2]);
        t3a[0][3] = fma2(t1v.y, w0, t3a[0][3]); t3a[1][3] = fma2(t1v.y, w1, t3a[1][3]);
    }

    // ---------------- fold C over this warp's 4 r-pairs ----------------
    // p[o][rp] = t1*t3 elementwise (packed over the r-pair)
    unsigned long long p[2][4];
    #pragma unroll
    for (int k = 0; k < 4; k++) {
        p[0][k] = mul2(t1a[0][k], t3a[0][k]);
        p[1][k] = mul2(t1a[1][k], t3a[1][k]);
    }

    // oaccR[c][o]: packed partial sums (even-r half, odd-r half)
    unsigned long long oaccR[DD][2];
    #pragma unroll
    for (int c = 0; c < DD; c++) oaccR[c][0] = oaccR[c][1] = 0ull;

    #pragma unroll
    for (int rp = 0; rp < 4; rp++) {
        const unsigned long long* cbase = &sm.s.CsP[(g * 4 + rp) * 18];
        #pragma unroll
        for (int c2 = 0; c2 < 8; c2++) {
            ulonglong2 cc = *(const ulonglong2*)(cbase + c2 * 2);       // warp-uniform
            int c = c2 * 2;
            oaccR[c][0]     = fma2(cc.x, p[0][rp], oaccR[c][0]);
            oaccR[c][1]     = fma2(cc.x, p[1][rp], oaccR[c][1]);
            oaccR[c + 1][0] = fma2(cc.y, p[0][rp], oaccR[c + 1][0]);
            oaccR[c + 1][1] = fma2(cc.y, p[1][rp], oaccR[c + 1][1]);
        }
    }

    // horizontal add of the two packed halves -> scalar partials
    float oacc[DD][2];
    #pragma unroll
    for (int c = 0; c < DD; c++) {
        float2 u0 = unpack2(oaccR[c][0]);
        float2 u1 = unpack2(oaccR[c][1]);
        oacc[c][0] = u0.x + u0.y;
        oacc[c][1] = u1.x + u1.y;
    }

    // ---------------- cross-warp reduction over 8 r-groups ----------------
    __syncthreads();   // everyone done reading scratch before aliasing red over it
    #pragma unroll
    for (int c = 0; c < DD; c++)
        *(float2*)&sm.red[g * (DD * CO) + c * CO + oo] = make_float2(oacc[c][0], oacc[c][1]);
    __syncthreads();

    {
        int c  = tid >> 4;
        int o0 = (tid & 15) * 4;
        float4 s = *(const float4*)&sm.red[c * CO + o0];
        #pragma unroll
        for (int gg = 1; gg < 8; gg++) {
            float4 t = *(const float4*)&sm.red[gg * (DD * CO) + c * CO + o0];
            s.x += t.x; s.y += t.y; s.z += t.z; s.w += t.w;
        }
        *(float4*)(out + (size_t)b * DD * CO + c * CO + o0) = s;
    }
}

extern "C" void kernel_launch(void* const* d_in, const int* in_sizes, int n_in,
                              void* d_out, int out_size)
{
    const float* x1 = (const float*)d_in[0];  // (32768, 16, 64)
    const float* x2 = (const float*)d_in[1];  // (32768, 16, 32)
    const float* w  = (const float*)d_in[2];  // (32768, 64, 32)
    const float* A  = (const float*)d_in[3];  // (16, 64)
    const float* B  = (const float*)d_in[4];  // (16, 64)
    const float* C  = (const float*)d_in[5];  // (16, 64)
    float* out = (float*)d_out;               // (32768, 16, 64)

    cp_tp_kernel<<<BATCH, 256>>>(x1, x2, w, A, B, C, out);
}

// round 6
// speedup vs baseline: 1.7287x; 1.7287x over previous
#include <cuda_runtime.h>
#include <cstdint>

#define BATCH  32768

// out[b,c,o] = sum_r C[c,r] * t1[b,r,o] * t3[b,r,o]
//   t1[r,o] = sum_i A[i,r] x1[i,o]        (M=r64, N=o64, K=i16)
//   t2[r,v] = sum_i B[i,r] x2[i,v]        (M=r64, N=v32, K=i16)
//   t3[r,o] = sum_v t2[r,v] w[o,v]        (M=r64, N=o64, K=v32)
//   out[c,o]= sum_r C[c,r] p[r,o]         (M=c16, N=o64, K=r64)  p = t1 .* t3
//
// tf32 mma.sync.m16n8k8, one CTA (128 thr / 4 warps) per batch element.
// All operands pre-packed in smem in fragment order so every fragment load is
// ONE bank-conflict-free LDS.128:
//  A-type float4 @ ((mtile*8+g)*KT + (kt^(g&1)))*4 + j =
//      { A[16mt+g][8kt+j], A[16mt+g+8][8kt+j], A[16mt+g][8kt+j+4], A[16mt+g+8][8kt+j+4] }
//  B-type float4 @ ((n)*KTH + (kth^(g&1)))*4 + j =
//      { B[n][16kth+j], B[n][16kth+j+4], B[n][16kth+j+8], B[n][16kth+j+12] }
//      (covers b0,b1 of two consecutive k-tiles; n = ntile*8+g)

__device__ __forceinline__ uint32_t f2tf(float x) {
    uint32_t r;
    asm("cvt.rna.tf32.f32 %0, %1;" : "=r"(r) : "f"(x));
    return r;
}

__device__ __forceinline__ void mma8(float* c, uint4 a, uint32_t b0, uint32_t b1) {
    asm volatile(
        "mma.sync.aligned.m16n8k8.row.col.f32.tf32.tf32.f32 "
        "{%0,%1,%2,%3}, {%4,%5,%6,%7}, {%8,%9}, {%0,%1,%2,%3};"
        : "+f"(c[0]), "+f"(c[1]), "+f"(c[2]), "+f"(c[3])
        : "r"(a.x), "r"(a.y), "r"(a.z), "r"(a.w), "r"(b0), "r"(b1));
}

__global__ __launch_bounds__(128, 4)
void cp_tp_tc(const float* __restrict__ x1,
              const float* __restrict__ x2,
              const float* __restrict__ w,
              const float* __restrict__ A,
              const float* __restrict__ Bm,
              const float* __restrict__ Cm,
              float* __restrict__ out)
{
    const int b    = blockIdx.x;
    const int tid  = threadIdx.x;
    const int lane = tid & 31;
    const int wid  = tid >> 5;      // 0..3
    const int g    = lane >> 2;     // 0..7  (mma group id)
    const int j    = lane & 3;      // 0..3  (thread-in-group)

    __shared__ union {
        struct {
            uint4 ApackA[256];      // A^T  [r][i]  KT=2   4KB
            uint4 ApackB[256];      // B^T  [r][i]  KT=2   4KB
            uint4 x1pack[256];      // x1^T [o][i]  KTH=1  4KB
            uint4 x2pack[128];      // x2^T [v][i]  KTH=1  2KB
            uint4 wpack [512];      // w    [o][v]  KTH=2  8KB
        } p1;                       // dead after t1/t3 -> aliased by ppack
        uint4 ppack[4][256];        // per-warp p [o16][r]  KTH=4  4KB each
    } u;
    __shared__ uint4 t2pack[512];   // t2 [r][v]  KT=4  8KB  (persistent)
    __shared__ uint4 Cpack [256];   // C  [c][r]  KT=8  4KB  (persistent)

    const float* x1g = x1 + (size_t)b * 1024;
    const float* x2g = x2 + (size_t)b * 512;
    const float* wg  = w  + (size_t)b * 2048;

    uint32_t* ApA = (uint32_t*)u.p1.ApackA;
    uint32_t* ApB = (uint32_t*)u.p1.ApackB;
    uint32_t* X1  = (uint32_t*)u.p1.x1pack;
    uint32_t* X2  = (uint32_t*)u.p1.x2pack;
    uint32_t* Wp  = (uint32_t*)u.p1.wpack;
    uint32_t* Cp  = (uint32_t*)Cpack;
    uint32_t* T2  = (uint32_t*)t2pack;

    // ================= pack stage (coalesced gmem reads, scatter STS) ======
    // A, B: element (m=r, k=i), KT=2
    #pragma unroll
    for (int t = 0; t < 8; t++) {
        int e = tid + t * 128;                 // e < 1024
        int i = e >> 6, r = e & 63;
        int mt = r >> 4, rm = r & 15, gg = rm & 7, up = rm >> 3;
        int kt = i >> 3, km = i & 7;
        int sidx = ((((mt * 8 + gg) * 2 + (kt ^ (gg & 1))) * 4 + (km & 3)) << 2)
                   + 2 * (km >> 2) + up;
        ApA[sidx] = f2tf(A[e]);
        ApB[sidx] = f2tf(Bm[e]);
    }
    // C: element (m=c, k=r), KT=8 (single m-tile)
    #pragma unroll
    for (int t = 0; t < 8; t++) {
        int e = tid + t * 128;
        int c = e >> 6, r = e & 63;
        int gg = c & 7, up = c >> 3;
        int kt = r >> 3, km = r & 7;
        int sidx = (((gg * 8 + (kt ^ (gg & 1))) * 4 + (km & 3)) << 2)
                   + 2 * (km >> 2) + up;
        Cp[sidx] = f2tf(Cm[e]);
    }
    // x1: B-type (n=o, k=i), KTH=1
    #pragma unroll
    for (int t = 0; t < 8; t++) {
        int e = tid + t * 128;
        int i = e >> 6, o = e & 63;
        X1[(((o << 2) + (i & 3)) << 2) + (i >> 2)] = f2tf(x1g[e]);
    }
    // x2: B-type (n=v, k=i), KTH=1
    #pragma unroll
    for (int t = 0; t < 4; t++) {
        int e = tid + t * 128;                 // e < 512
        int i = e >> 5, v = e & 31;
        X2[(((v << 2) + (i & 3)) << 2) + (i >> 2)] = f2tf(x2g[e]);
    }
    // w: B-type (n=o, k=v), KTH=2
    #pragma unroll
    for (int t = 0; t < 16; t++) {
        int e = tid + t * 128;                 // e < 2048
        int o = e >> 5, v = e & 31;
        int gg = o & 7;
        int kth = v >> 4, km = v & 15;
        int sidx = (((o * 2 + (kth ^ (gg & 1))) * 4 + (km & 3)) << 2) + (km >> 2);
        Wp[sidx] = f2tf(wg[e]);
    }
    __syncthreads();

    // ================= t2 = B^T @ x2^T : warp owns m-tile = wid ============
    {
        float t2acc[4][4];
        #pragma unroll
        for (int nt = 0; nt < 4; nt++)
            #pragma unroll
            for (int q = 0; q < 4; q++) t2acc[nt][q] = 0.f;

        uint4 bf[4];
        #pragma unroll
        for (int nt = 0; nt < 4; nt++)
            bf[nt] = u.p1.x2pack[((nt * 8 + g) << 2) + j];

        #pragma unroll
        for (int kt = 0; kt < 2; kt++) {
            uint4 af = u.p1.ApackB[(((wid * 8 + g) * 2 + (kt ^ (g & 1))) << 2) + j];
            #pragma unroll
            for (int nt = 0; nt < 4; nt++)
                mma8(t2acc[nt], af, kt ? bf[nt].z : bf[nt].x,
                                    kt ? bf[nt].w : bf[nt].y);
        }
        // store warp's 16x32 slice of t2 into A-type pack (KT=4), tf32-converted
        #pragma unroll
        for (int nt = 0; nt < 4; nt++) {
            #pragma unroll
            for (int q = 0; q < 4; q++) {
                int up = q >> 1, dc = q & 1;
                int km = 2 * j + dc;           // v & 7
                int sidx = ((((wid * 8 + g) * 4 + (nt ^ (g & 1))) * 4 + (km & 3)) << 2)
                           + 2 * (km >> 2) + up;
                T2[sidx] = f2tf(t2acc[nt][q]);
            }
        }
    }
    __syncthreads();

    // ================= t1 & t3 : warp owns o-slice [wid*16, wid*16+16) =====
    float t1acc[4][2][4], t3acc[4][2][4];
    #pragma unroll
    for (int mt = 0; mt < 4; mt++)
        #pragma unroll
        for (int ntl = 0; ntl < 2; ntl++)
            #pragma unroll
            for (int q = 0; q < 4; q++) { t1acc[mt][ntl][q] = 0.f; t3acc[mt][ntl][q] = 0.f; }

    uint4 x1f[2], wf[2][2];
    #pragma unroll
    for (int ntl = 0; ntl < 2; ntl++) {
        int n = (2 * wid + ntl) * 8 + g;
        x1f[ntl] = u.p1.x1pack[(n << 2) + j];
        #pragma unroll
        for (int kth = 0; kth < 2; kth++)
            wf[ntl][kth] = u.p1.wpack[((n * 2 + (kth ^ (g & 1))) << 2) + j];
    }

    #pragma unroll
    for (int mt = 0; mt < 4; mt++) {
        #pragma unroll
        for (int kt = 0; kt < 2; kt++) {
            uint4 af = u.p1.ApackA[(((mt * 8 + g) * 2 + (kt ^ (g & 1))) << 2) + j];
            #pragma unroll
            for (int ntl = 0; ntl < 2; ntl++)
                mma8(t1acc[mt][ntl], af, kt ? x1f[ntl].z : x1f[ntl].x,
                                         kt ? x1f[ntl].w : x1f[ntl].y);
        }
        #pragma unroll
        for (int kt = 0; kt < 4; kt++) {
            uint4 af = t2pack[(((mt * 8 + g) * 4 + (kt ^ (g & 1))) << 2) + j];
            #pragma unroll
            for (int ntl = 0; ntl < 2; ntl++) {
                uint4 bv = wf[ntl][kt >> 1];
                mma8(t3acc[mt][ntl], af, (kt & 1) ? bv.z : bv.x,
                                         (kt & 1) ? bv.w : bv.y);
            }
        }
    }
    __syncthreads();   // all warps done with phase1 buffers -> alias as ppack

    // ================= p = t1 .* t3 -> per-warp B-type pack (KTH=4) ========
    {
        uint32_t* PP = (uint32_t*)u.ppack[wid];
        #pragma unroll
        for (int mt = 0; mt < 4; mt++) {
            #pragma unroll
            for (int ntl = 0; ntl < 2; ntl++) {
                #pragma unroll
                for (int q = 0; q < 4; q++) {
                    int up = q >> 1, dc = q & 1;
                    float p = t1acc[mt][ntl][q] * t3acc[mt][ntl][q];
                    int g2 = 2 * j + dc;                    // n & 7 (local o)
                    int sidx = ((((ntl * 8 + g2) * 4 + (mt ^ (g2 & 1))) * 4 + (g & 3)) << 2)
                               + (g >> 2) + 2 * up;
                    PP[sidx] = f2tf(p);
                }
            }
        }
    }
    __syncwarp();

    // ================= out = C @ p (M=c16, N=o16, K=r64) ===================
    {
        float oacc[2][4];
        #pragma unroll
        for (int ntl = 0; ntl < 2; ntl++)
            #pragma unroll
            for (int q = 0; q < 4; q++) oacc[ntl][q] = 0.f;

        uint4 pf[2][4];
        #pragma unroll
        for (int ntl = 0; ntl < 2; ntl++)
            #pragma unroll
            for (int kth = 0; kth < 4; kth++)
                pf[ntl][kth] = u.ppack[wid][(((ntl * 8 + g) * 4 + (kth ^ (g & 1))) << 2) + j];

        #pragma unroll
        for (int kt = 0; kt < 8; kt++) {
            uint4 af = Cpack[((g * 8 + (kt ^ (g & 1))) << 2) + j];
            #pragma unroll
            for (int ntl = 0; ntl < 2; ntl++) {
                uint4 bv = pf[ntl][kt >> 1];
                mma8(oacc[ntl], af, (kt & 1) ? bv.z : bv.x,
                                    (kt & 1) ? bv.w : bv.y);
            }
        }

        float* og = out + (size_t)b * 1024;
        #pragma unroll
        for (int ntl = 0; ntl < 2; ntl++) {
            #pragma unroll
            for (int up = 0; up < 2; up++) {
                int c  = g + 8 * up;
                int o0 = wid * 16 + 8 * ntl + 2 * j;
                *(float2*)&og[c * 64 + o0] =
                    make_float2(oacc[ntl][2 * up], oacc[ntl][2 * up + 1]);
            }
        }
    }
}

extern "C" void kernel_launch(void* const* d_in, const int* in_sizes, int n_in,
                              void* d_out, int out_size)
{
    const float* x1 = (const float*)d_in[0];  // (32768, 16, 64)
    const float* x2 = (const float*)d_in[1];  // (32768, 16, 32)
    const float* w  = (const float*)d_in[2];  // (32768, 64, 32)
    const float* A  = (const float*)d_in[3];  // (16, 64)
    const float* B  = (const float*)d_in[4];  // (16, 64)
    const float* C  = (const float*)d_in[5];  // (16, 64)
    float* out = (float*)d_out;               // (32768, 16, 64)

    cp_tp_tc<<<BATCH, 128>>>(x1, x2, w, A, B, C, out);
}

// round 12
// speedup vs baseline: 2.8864x; 1.6697x over previous
#include <cuda_runtime.h>
#include <cstdint>

#define BATCH  32768

// out[b,c,o] = sum_r C[c,r] * t1[b,r,o] * t3[b,r,o]
//   t1[r,o] = sum_i A[i,r] x1[i,o]        (M=r64, N=o64, K=i16)
//   t2[r,v] = sum_i B[i,r] x2[i,v]        (M=r64, N=v32, K=i16)
//   t3[r,o] = sum_v t2[r,v] w[o,v]        (M=r64, N=o64, K=v32)
//   out[c,o]= sum_r C[c,r] p[r,o]         (M=c16, N=o64, K=r64)  p = t1 .* t3
//
// tf32 m16n8k8 mma. One CTA (128 thr / 4 warps) per batch element.
// Batch-invariant A/B/C are pre-packed ONCE per launch into __device__ globals
// in exact fragment order -> main kernel loads them as LDG.128 (L2 broadcast).
// Batch tensors x1/x2/w go through smem in bank-conflict-free remapped-transpose
// layouts; all fragment gathers are conflict-free LDS.32/LDS.128.

__device__ __forceinline__ uint32_t f2tf(float x) {
    uint32_t r;
    asm("cvt.rna.tf32.f32 %0, %1;" : "=r"(r) : "f"(x));
    return r;
}

__device__ __forceinline__ void mma8(float* c, uint4 a, uint32_t b0, uint32_t b1) {
    asm volatile(
        "mma.sync.aligned.m16n8k8.row.col.f32.tf32.tf32.f32 "
        "{%0,%1,%2,%3}, {%4,%5,%6,%7}, {%8,%9}, {%0,%1,%2,%3};"
        : "+f"(c[0]), "+f"(c[1]), "+f"(c[2]), "+f"(c[3])
        : "r"(a.x), "r"(a.y), "r"(a.z), "r"(a.w), "r"(b0), "r"(b1));
}

// Prepacked fragment stores (uint4 = one thread's A-operand fragment).
// A/B slot: [mt*2+kt][g][j], words w: (up=w&1, kh=w>>1) -> elem [16mt+g+8up][8kt+j+4kh]
// C   slot: [kt(0..7)][g][j], words    -> elem C[g+8up][8kt+j+4kh]
__device__ uint4 g_Apack[256];
__device__ uint4 g_Bpack[256];
__device__ uint4 g_Cpack[256];

__global__ void pack_abc_kernel(const float* __restrict__ A,
                                const float* __restrict__ B,
                                const float* __restrict__ C)
{
    int s = blockIdx.x * blockDim.x + threadIdx.x;   // 0..3071
    if (s >= 3072) return;
    int w  = s & 3;
    int j  = (s >> 2) & 3;
    int g  = (s >> 4) & 7;
    int kf = (s >> 7) & 7;
    int m  = s >> 10;                                // 0=A 1=B 2=C
    int up = w & 1, kh = w >> 1;
    float v;
    uint32_t* dst;
    if (m < 2) {
        int i = 8 * (kf & 1) + j + 4 * kh;
        int r = 16 * (kf >> 1) + g + 8 * up;
        v = (m == 0 ? A : B)[i * 64 + r];
        dst = (m == 0) ? (uint32_t*)g_Apack : (uint32_t*)g_Bpack;
    } else {
        int c = g + 8 * up;
        int r = 8 * kf + j + 4 * kh;
        v = C[c * 64 + r];
        dst = (uint32_t*)g_Cpack;
    }
    dst[s & 1023] = f2tf(v);
}

__global__ __launch_bounds__(128, 5)
void cp_tp_tc2(const float* __restrict__ x1,
               const float* __restrict__ x2,
               const float* __restrict__ w,
               float* __restrict__ out)
{
    const int b    = blockIdx.x;
    const int tid  = threadIdx.x;
    const int lane = tid & 31;
    const int wid  = tid >> 5;      // 0..3
    const int g    = lane >> 2;     // 0..7
    const int j    = lane & 3;      // 0..3

    // conflict-free remapped-transpose layouts (word addresses, fp32 words)
    __shared__ uint32_t sx1[16 * 66];        // x1: word = (4(i&3)+(i>>2))*66 + o
    __shared__ uint32_t sx2[16 * 34];        // x2: word = (4(i&3)+(i>>2))*34 + v
    __shared__ uint32_t sw_[2048];           // w:  packed B-frag layout (LDS.128)
    __shared__ uint32_t st2[32 * 66];        // t2: word = F(v)*66 + r
    __shared__ uint32_t sp[4][64 * 18];      // p (per warp): word = G(r)*18 + o_local

    const float* x1g = x1 + (size_t)b * 1024;
    const float* x2g = x2 + (size_t)b * 512;
    const float* wg  = w  + (size_t)b * 2048;

    // Prefetch the fragments needed right after the first barrier so their
    // gmem latency overlaps the staging stores below.
    uint4 bpf0 = g_Bpack[(wid * 2 + 0) * 32 + g * 4 + j];
    uint4 bpf1 = g_Bpack[(wid * 2 + 1) * 32 + g * 4 + j];
    uint4 apf0 = g_Apack[g * 4 + j];        // mt=0, kt=0 slot

    // ---------------- stage x1/x2/w into smem (conflict-free STS.32) -------
    #pragma unroll
    for (int t = 0; t < 8; t++) {            // x1: i fixed per warp-instr, o 32-consec
        int e = tid + t * 128;
        int i = e >> 6, o = e & 63;
        sx1[(4 * (i & 3) + (i >> 2)) * 66 + o] = f2tf(x1g[e]);
    }
    #pragma unroll
    for (int t = 0; t < 4; t++) {            // x2
        int e = tid + t * 128;
        int i = e >> 5, v = e & 31;
        sx2[(4 * (i & 3) + (i >> 2)) * 34 + v] = f2tf(x2g[e]);
    }
    #pragma unroll
    for (int t = 0; t < 16; t++) {           // w: o fixed per warp-instr, v 0..31 (CF)
        int e = tid + t * 128;
        int o = e >> 5, v = e & 31;
        int kth = v >> 4, km = v & 15;
        sw_[((o * 2 + (kth ^ (o & 1))) * 4 + (km & 3)) * 4 + (km >> 2)] = f2tf(wg[e]);
    }
    __syncthreads();

    // ---------------- t2 = B^T @ x2^T : warp owns m-tile = wid -------------
    {
        uint32_t bfr[4][4];
        #pragma unroll
        for (int nt = 0; nt < 4; nt++)
            #pragma unroll
            for (int s2 = 0; s2 < 4; s2++)                 // i = j + 4*s2
                bfr[nt][s2] = sx2[(4 * j + s2) * 34 + nt * 8 + g];

        float t2acc[4][4];
        #pragma unroll
        for (int nt = 0; nt < 4; nt++)
            #pragma unroll
            for (int q = 0; q < 4; q++) t2acc[nt][q] = 0.f;

        #pragma unroll
        for (int nt = 0; nt < 4; nt++)
            mma8(t2acc[nt], bpf0, bfr[nt][0], bfr[nt][1]);
        #pragma unroll
        for (int nt = 0; nt < 4; nt++)
            mma8(t2acc[nt], bpf1, bfr[nt][2], bfr[nt][3]);

        // store t2: F(v) = 16(v>>4) + 4(v&3) + 2((v>>3)&1) + ((v>>2)&1)
        #pragma unroll
        for (int nt = 0; nt < 4; nt++) {
            #pragma unroll
            for (int q = 0; q < 4; q++) {
                int up = q >> 1, dc = q & 1;
                int v  = nt * 8 + 2 * j + dc;
                int F  = 16 * (v >> 4) + 4 * (v & 3) + 2 * ((v >> 3) & 1) + ((v >> 2) & 1);
                st2[F * 66 + wid * 16 + g + 8 * up] = f2tf(t2acc[nt][q]);
            }
        }
    }
    __syncthreads();

    // ---------------- persistent B-frags for this warp's o-slice -----------
    uint32_t x1f[2][4];
    uint4    wf[2][2];
    #pragma unroll
    for (int ntl = 0; ntl < 2; ntl++) {
        int n = (2 * wid + ntl) * 8 + g;
        #pragma unroll
        for (int s2 = 0; s2 < 4; s2++)
            x1f[ntl][s2] = sx1[(4 * j + s2) * 66 + n];
        #pragma unroll
        for (int kth = 0; kth < 2; kth++)
            wf[ntl][kth] = ((const uint4*)sw_)[(n * 2 + (kth ^ (g & 1))) * 4 + j];
    }

    // ---------------- streamed mt loop: t1, t3, p --------------------------
    uint32_t* pw = sp[wid];
    #pragma unroll
    for (int mt = 0; mt < 4; mt++) {
        float t1a[2][4], t3a[2][4];
        #pragma unroll
        for (int ntl = 0; ntl < 2; ntl++)
            #pragma unroll
            for (int q = 0; q < 4; q++) { t1a[ntl][q] = 0.f; t3a[ntl][q] = 0.f; }

        #pragma unroll
        for (int kt = 0; kt < 2; kt++) {
            uint4 af = (mt == 0 && kt == 0)
                       ? apf0
                       : g_Apack[(mt * 2 + kt) * 32 + g * 4 + j];  // L2 broadcast
            #pragma unroll
            for (int ntl = 0; ntl < 2; ntl++)
                mma8(t1a[ntl], af, x1f[ntl][2 * kt], x1f[ntl][2 * kt + 1]);
        }
        #pragma unroll
        for (int kt = 0; kt < 4; kt++) {
            // t2 A-frag: rows 16mt+g(+8), cols 8kt+j(+4); conflict-free LDS.32 x4
            int base = (16 * (kt >> 1) + 4 * j + 2 * (kt & 1)) * 66 + 16 * mt + g;
            uint4 tf;
            tf.x = st2[base];            // kh=0 up=0
            tf.y = st2[base + 8];        // kh=0 up=1
            tf.z = st2[base + 66];       // kh=1 up=0  (F+1)
            tf.w = st2[base + 66 + 8];   // kh=1 up=1
            #pragma unroll
            for (int ntl = 0; ntl < 2; ntl++) {
                uint4 bv = wf[ntl][kt >> 1];
                mma8(t3a[ntl], tf, (kt & 1) ? bv.z : bv.x,
                                   (kt & 1) ? bv.w : bv.y);
            }
        }
        // p = t1 .* t3 -> per-warp smem, G(r) = 16(r>>4) + 4(r&3) + ((r>>2)&3)
        #pragma unroll
        for (int ntl = 0; ntl < 2; ntl++) {
            #pragma unroll
            for (int q = 0; q < 4; q++) {
                int up = q >> 1, dc = q & 1;
                int G  = 16 * mt + 4 * (g & 3) + (g >> 2) + 2 * up;
                pw[G * 18 + 8 * ntl + 2 * j + dc] = f2tf(t1a[ntl][q] * t3a[ntl][q]);
            }
        }
    }
    __syncwarp();

    // ---------------- out = C @ p  (M=c16, N=o16, K=r64) -------------------
    {
        float oacc[2][4];
        #pragma unroll
        for (int ntl = 0; ntl < 2; ntl++)
            #pragma unroll
            for (int q = 0; q < 4; q++) oacc[ntl][q] = 0.f;

        #pragma unroll
        for (int kt = 0; kt < 8; kt++) {
            uint4 cf = g_Cpack[kt * 32 + g * 4 + j];               // L2 broadcast
            int Gb = (16 * (kt >> 1) + 4 * j + 2 * (kt & 1)) * 18;
            #pragma unroll
            for (int ntl = 0; ntl < 2; ntl++) {
                int o = 8 * ntl + g;
                mma8(oacc[ntl], cf, pw[Gb + o], pw[Gb + 18 + o]);
            }
        }

        float* og = out + (size_t)b * 1024;
        #pragma unroll
        for (int ntl = 0; ntl < 2; ntl++) {
            #pragma unroll
            for (int up = 0; up < 2; up++) {
                int c  = g + 8 * up;
                int o0 = wid * 16 + 8 * ntl + 2 * j;
                *(float2*)&og[c * 64 + o0] =
                    make_float2(oacc[ntl][2 * up], oacc[ntl][2 * up + 1]);
            }
        }
    }
}

extern "C" void kernel_launch(void* const* d_in, const int* in_sizes, int n_in,
                              void* d_out, int out_size)
{
    const float* x1 = (const float*)d_in[0];  // (32768, 16, 64)
    const float* x2 = (const float*)d_in[1];  // (32768, 16, 32)
    const float* w  = (const float*)d_in[2];  // (32768, 64, 32)
    const float* A  = (const float*)d_in[3];  // (16, 64)
    const float* B  = (const float*)d_in[4];  // (16, 64)
    const float* C  = (const float*)d_in[5];  // (16, 64)
    float* out = (float*)d_out;               // (32768, 16, 64)

    pack_abc_kernel<<<3, 1024>>>(A, B, C);
    cp_tp_tc2<<<BATCH, 128>>>(x1, x2, w, out);
}

// round 13
// speedup vs baseline: 3.0706x; 1.0638x over previous
#include <cuda_runtime.h>
#include <cstdint>

#define BATCH  32768

// out[b,c,o] = sum_r C[c,r] * t1[b,r,o] * t3[b,r,o]
//   t1[r,o] = sum_i A[i,r] x1[i,o]     t2[r,v] = sum_i B[i,r] x2[i,v]
//   t3[r,o] = sum_v t2[r,v] w[o,v]     out[c,o]= sum_r C[c,r] (t1.*t3)[r,o]
//
// tf32 m16n8k8. One CTA = 64 threads = 2 warps per batch element; warp wid owns
// r-tiles {2wid, 2wid+1} for t2/t1/t3/p and o-slice [32wid,32wid+32) for out.
//
// KEY TRICK: B-operands (x2, x1, w) are fed with n-columns permuted by
// pi(p) = (p>>1) + 4(p&1) within each 8-block. Then the mma accumulator column
// layout (2j+dc) maps to logical col j+4dc — exactly the A-fragment k-layout —
// so t2 accumulators ARE the t3 A-fragments: t2 never touches smem.

__device__ __forceinline__ uint32_t f2tf(float x) {
    uint32_t r;
    asm("cvt.rna.tf32.f32 %0, %1;" : "=r"(r) : "f"(x));
    return r;
}

__device__ __forceinline__ void mma8(float* c, uint4 a, uint32_t b0, uint32_t b1) {
    asm volatile(
        "mma.sync.aligned.m16n8k8.row.col.f32.tf32.tf32.f32 "
        "{%0,%1,%2,%3}, {%4,%5,%6,%7}, {%8,%9}, {%0,%1,%2,%3};"
        : "+f"(c[0]), "+f"(c[1]), "+f"(c[2]), "+f"(c[3])
        : "r"(a.x), "r"(a.y), "r"(a.z), "r"(a.w), "r"(b0), "r"(b1));
}

// Prepacked A-operand fragments (uint4 per thread-slot).
// A/B slot: [mt*2+kt][g][j], words w=(up=w&1,kh=w>>1) -> elem [16mt+g+8up][8kt+j+4kh]
// C   slot: [kt(0..7)][g][j]                          -> elem C[g+8up][8kt+j+4kh]
__device__ uint4 g_Apack[256];
__device__ uint4 g_Bpack[256];
__device__ uint4 g_Cpack[256];

__global__ void pack_abc_kernel(const float* __restrict__ A,
                                const float* __restrict__ B,
                                const float* __restrict__ C)
{
    int s = blockIdx.x * blockDim.x + threadIdx.x;   // 0..3071
    if (s >= 3072) return;
    int w  = s & 3;
    int j  = (s >> 2) & 3;
    int g  = (s >> 4) & 7;
    int kf = (s >> 7) & 7;
    int m  = s >> 10;                                // 0=A 1=B 2=C
    int up = w & 1, kh = w >> 1;
    float v;
    uint32_t* dst;
    if (m < 2) {
        int i = 8 * (kf & 1) + j + 4 * kh;
        int r = 16 * (kf >> 1) + g + 8 * up;
        v = (m == 0 ? A : B)[i * 64 + r];
        dst = (m == 0) ? (uint32_t*)g_Apack : (uint32_t*)g_Bpack;
    } else {
        int c = g + 8 * up;
        int r = 8 * kf + j + 4 * kh;
        v = C[c * 64 + r];
        dst = (uint32_t*)g_Cpack;
    }
    dst[s & 1023] = f2tf(v);
}

__global__ __launch_bounds__(64, 7)
void cp_tp_tc3(const float* __restrict__ x1,
               const float* __restrict__ x2,
               const float* __restrict__ w,
               float* __restrict__ out)
{
    const int b    = blockIdx.x;
    const int tid  = threadIdx.x;          // 0..63
    const int lane = tid & 31;
    const int wid  = tid >> 5;             // 0..1
    const int g    = lane >> 2;            // 0..7
    const int j    = lane & 3;             // 0..3
    const int pig  = (g >> 1) + 4 * (g & 1);   // pi(g)

    __shared__ uint32_t sx1[16 * 66];      // word = (4(i&3)+(i>>2))*66 + o
    __shared__ uint32_t sx2[16 * 34];      // word = (4(i&3)+(i>>2))*34 + v
    __shared__ uint32_t sw_[2048];         // B-frag packed, swizzle bit (o>>2)&1
    __shared__ uint32_t sp [64 * 68];      // p: word = o*68 + r  (CF both sides)

    const float* x1g = x1 + (size_t)b * 1024;
    const float* x2g = x2 + (size_t)b * 512;
    const float* wg  = w  + (size_t)b * 2048;

    // prefetch batch-invariant fragments (overlap with staging)
    uint4 apf[2][2], bpf[2][2];
    #pragma unroll
    for (int mtl = 0; mtl < 2; mtl++)
        #pragma unroll
        for (int kt = 0; kt < 2; kt++) {
            int mt = 2 * wid + mtl;
            apf[mtl][kt] = g_Apack[(mt * 2 + kt) * 32 + g * 4 + j];
            bpf[mtl][kt] = g_Bpack[(mt * 2 + kt) * 32 + g * 4 + j];
        }

    // ---------------- stage x1/x2/w (coalesced LDG, CF STS.32) -------------
    #pragma unroll
    for (int t = 0; t < 16; t++) {
        int e = tid + t * 64;
        int i = e >> 6, o = e & 63;
        sx1[(4 * (i & 3) + (i >> 2)) * 66 + o] = f2tf(x1g[e]);
    }
    #pragma unroll
    for (int t = 0; t < 8; t++) {
        int e = tid + t * 64;
        int i = e >> 5, v = e & 31;
        sx2[(4 * (i & 3) + (i >> 2)) * 34 + v] = f2tf(x2g[e]);
    }
    #pragma unroll
    for (int t = 0; t < 32; t++) {
        int e = tid + t * 64;
        int o = e >> 5, v = e & 31;
        int swb = (o >> 2) & 1;
        sw_[(((o * 2 + ((v >> 4) ^ swb)) * 4 + (v & 3)) << 2) + ((v >> 2) & 3)]
            = f2tf(wg[e]);
    }
    __syncthreads();

    // ---------------- t2 (pi-permuted B cols) -> registers as A-frags ------
    uint4 t2f[2][4];          // [mtl][kt] A-frag for t3
    {
        uint32_t bfr[4][4];   // x2 B-frags: [nt][s2], i = 4*s2 + j
        #pragma unroll
        for (int nt = 0; nt < 4; nt++)
            #pragma unroll
            for (int s2 = 0; s2 < 4; s2++)
                bfr[nt][s2] = sx2[(4 * j + s2) * 34 + pig + 8 * nt];

        #pragma unroll
        for (int mtl = 0; mtl < 2; mtl++) {
            float acc[4][4];
            #pragma unroll
            for (int nt = 0; nt < 4; nt++)
                #pragma unroll
                for (int q = 0; q < 4; q++) acc[nt][q] = 0.f;
            #pragma unroll
            for (int kt2 = 0; kt2 < 2; kt2++)
                #pragma unroll
                for (int nt = 0; nt < 4; nt++)
                    mma8(acc[nt], bpf[mtl][kt2], bfr[nt][2 * kt2], bfr[nt][2 * kt2 + 1]);
            // acc[nt] holds t2[16mt+g+8up][ j+4dc+8nt ] -> reorder q {0,2,1,3}
            // gives A-frag word order (up,kh): kh == dc.
            #pragma unroll
            for (int nt = 0; nt < 4; nt++) {
                t2f[mtl][nt].x = f2tf(acc[nt][0]);
                t2f[mtl][nt].y = f2tf(acc[nt][2]);
                t2f[mtl][nt].z = f2tf(acc[nt][1]);
                t2f[mtl][nt].w = f2tf(acc[nt][3]);
            }
        }
    }

    // ---------------- t1 & t3 per (mtl, nt); p -> smem ---------------------
    const int swb = (pig >> 2) & 1;
    #pragma unroll
    for (int mtl = 0; mtl < 2; mtl++) {
        int mt = 2 * wid + mtl;
        #pragma unroll
        for (int nt = 0; nt < 8; nt++) {
            float t1a[4] = {0.f, 0.f, 0.f, 0.f};
            float t3a[4] = {0.f, 0.f, 0.f, 0.f};

            uint32_t x1b[4];                       // x1 B-frags, i = 4*s + j
            #pragma unroll
            for (int s = 0; s < 4; s++)
                x1b[s] = sx1[(4 * j + s) * 66 + pig + 8 * nt];
            mma8(t1a, apf[mtl][0], x1b[0], x1b[1]);
            mma8(t1a, apf[mtl][1], x1b[2], x1b[3]);

            int opi = pig + 8 * nt;
            #pragma unroll
            for (int kth = 0; kth < 2; kth++) {
                uint4 wv4 = ((const uint4*)sw_)[(opi * 2 + (kth ^ swb)) * 4 + j];
                mma8(t3a, t2f[mtl][2 * kth],     wv4.x, wv4.y);
                mma8(t3a, t2f[mtl][2 * kth + 1], wv4.z, wv4.w);
            }

            // p[r=16mt+g+8up][o=j+4dc+8nt], tf32, CF store (banks 4j+g)
            #pragma unroll
            for (int q = 0; q < 4; q++) {
                int up = q >> 1, dc = q & 1;
                sp[(j + 4 * dc + 8 * nt) * 68 + 16 * mt + g + 8 * up]
                    = f2tf(t1a[q] * t3a[q]);
            }
        }
    }
    __syncthreads();

    // ---------------- out = C @ p  (warp o-slice [32wid, +32)) -------------
    {
        float oacc[4][4];
        #pragma unroll
        for (int nt = 0; nt < 4; nt++)
            #pragma unroll
            for (int q = 0; q < 4; q++) oacc[nt][q] = 0.f;

        #pragma unroll
        for (int kt = 0; kt < 8; kt++) {
            uint4 cf = g_Cpack[kt * 32 + g * 4 + j];
            #pragma unroll
            for (int nt = 0; nt < 4; nt++) {
                int o = 32 * wid + 8 * nt + g;          // identity n-mapping
                uint32_t b0 = sp[o * 68 + 8 * kt + j];      // banks 4g+j, CF
                uint32_t b1 = sp[o * 68 + 8 * kt + j + 4];
                mma8(oacc[nt], cf, b0, b1);
            }
        }

        float* og = out + (size_t)b * 1024;
        #pragma unroll
        for (int nt = 0; nt < 4; nt++) {
            #pragma unroll
            for (int up = 0; up < 2; up++) {
                int c  = g + 8 * up;
                int o0 = 32 * wid + 8 * nt + 2 * j;
                *(float2*)&og[c * 64 + o0] =
                    make_float2(oacc[nt][2 * up], oacc[nt][2 * up + 1]);
            }
        }
    }
}

extern "C" void kernel_launch(void* const* d_in, const int* in_sizes, int n_in,
                              void* d_out, int out_size)
{
    const float* x1 = (const float*)d_in[0];  // (32768, 16, 64)
    const float* x2 = (const float*)d_in[1];  // (32768, 16, 32)
    const float* w  = (const float*)d_in[2];  // (32768, 64, 32)
    const float* A  = (const float*)d_in[3];  // (16, 64)
    const float* B  = (const float*)d_in[4];  // (16, 64)
    const float* C  = (const float*)d_in[5];  // (16, 64)
    float* out = (float*)d_out;               // (32768, 16, 64)

    pack_abc_kernel<<<3, 1024>>>(A, B, C);
    cp_tp_tc3<<<BATCH, 64>>>(x1, x2, w, out);
}

// round 14
// speedup vs baseline: 3.4018x; 1.1078x over previous
#include <cuda_runtime.h>
#include <cstdint>

#define BATCH  32768

// out[b,c,o] = sum_r C[c,r] * t1[b,r,o] * t3[b,r,o]
//   t1[r,o] = sum_i A[i,r] x1[i,o]     t2[r,v] = sum_i B[i,r] x2[i,v]
//   t3[r,o] = sum_v t2[r,v] w[o,v]     out[c,o]= sum_r C[c,r] (t1.*t3)[r,o]
//
// tf32 m16n8k8. One CTA = 64 threads = 2 warps per batch element; warp wid owns
// r-tiles {2wid, 2wid+1} for t2/t1/t3/p and o-slice [32wid,32wid+32) for out.
//
// pi-trick: B-operands (x2, x1, w) are fed with n-columns permuted by
// pi(p) = (p>>1) + 4(p&1) within each 8-block, so the mma accumulator column
// layout (2j+dc) maps to logical col j+4dc = the A-fragment k-layout -> t2
// accumulators ARE the t3 A-fragments (t2 never touches smem).
//
// R14: nt-outer / mtl-inner loop so x1/w fragments are loaded ONCE per warp
// (they are mtl-invariant) — removes ~96 smem wavefronts per warp.

__device__ __forceinline__ uint32_t f2tf(float x) {
    uint32_t r;
    asm("cvt.rna.tf32.f32 %0, %1;" : "=r"(r) : "f"(x));
    return r;
}

__device__ __forceinline__ void mma8(float* c, uint4 a, uint32_t b0, uint32_t b1) {
    asm volatile(
        "mma.sync.aligned.m16n8k8.row.col.f32.tf32.tf32.f32 "
        "{%0,%1,%2,%3}, {%4,%5,%6,%7}, {%8,%9}, {%0,%1,%2,%3};"
        : "+f"(c[0]), "+f"(c[1]), "+f"(c[2]), "+f"(c[3])
        : "r"(a.x), "r"(a.y), "r"(a.z), "r"(a.w), "r"(b0), "r"(b1));
}

// Prepacked A-operand fragments (uint4 per thread-slot).
// A/B slot: [mt*2+kt][g][j], words w=(up=w&1,kh=w>>1) -> elem [16mt+g+8up][8kt+j+4kh]
// C   slot: [kt(0..7)][g][j]                          -> elem C[g+8up][8kt+j+4kh]
__device__ uint4 g_Apack[256];
__device__ uint4 g_Bpack[256];
__device__ uint4 g_Cpack[256];

__global__ void pack_abc_kernel(const float* __restrict__ A,
                                const float* __restrict__ B,
                                const float* __restrict__ C)
{
    int s = blockIdx.x * blockDim.x + threadIdx.x;   // 0..3071
    if (s >= 3072) return;
    int w  = s & 3;
    int j  = (s >> 2) & 3;
    int g  = (s >> 4) & 7;
    int kf = (s >> 7) & 7;
    int m  = s >> 10;                                // 0=A 1=B 2=C
    int up = w & 1, kh = w >> 1;
    float v;
    uint32_t* dst;
    if (m < 2) {
        int i = 8 * (kf & 1) + j + 4 * kh;
        int r = 16 * (kf >> 1) + g + 8 * up;
        v = (m == 0 ? A : B)[i * 64 + r];
        dst = (m == 0) ? (uint32_t*)g_Apack : (uint32_t*)g_Bpack;
    } else {
        int c = g + 8 * up;
        int r = 8 * kf + j + 4 * kh;
        v = C[c * 64 + r];
        dst = (uint32_t*)g_Cpack;
    }
    dst[s & 1023] = f2tf(v);
}

__global__ __launch_bounds__(64, 7)
void cp_tp_tc4(const float* __restrict__ x1,
               const float* __restrict__ x2,
               const float* __restrict__ w,
               float* __restrict__ out)
{
    const int b    = blockIdx.x;
    const int tid  = threadIdx.x;          // 0..63
    const int lane = tid & 31;
    const int wid  = tid >> 5;             // 0..1
    const int g    = lane >> 2;            // 0..7
    const int j    = lane & 3;             // 0..3
    const int pig  = (g >> 1) + 4 * (g & 1);   // pi(g)

    __shared__ uint32_t sx1[16 * 66];      // word = (4(i&3)+(i>>2))*66 + o
    __shared__ uint32_t sx2[16 * 34];      // word = (4(i&3)+(i>>2))*34 + v
    __shared__ uint32_t sw_[2048];         // B-frag packed, swizzle bit (o>>2)&1
    __shared__ uint32_t sp [64 * 68];      // p: word = o*68 + r  (CF loads, 2-way stores)

    const float* x1g = x1 + (size_t)b * 1024;
    const float* x2g = x2 + (size_t)b * 512;
    const float* wg  = w  + (size_t)b * 2048;

    // prefetch batch-invariant fragments (overlap with staging)
    uint4 apf[2][2], bpf[2][2];
    #pragma unroll
    for (int mtl = 0; mtl < 2; mtl++)
        #pragma unroll
        for (int kt = 0; kt < 2; kt++) {
            int mt = 2 * wid + mtl;
            apf[mtl][kt] = g_Apack[(mt * 2 + kt) * 32 + g * 4 + j];
            bpf[mtl][kt] = g_Bpack[(mt * 2 + kt) * 32 + g * 4 + j];
        }

    // ---------------- stage x1/x2/w (coalesced LDG, CF STS.32) -------------
    #pragma unroll
    for (int t = 0; t < 16; t++) {
        int e = tid + t * 64;
        int i = e >> 6, o = e & 63;
        sx1[(4 * (i & 3) + (i >> 2)) * 66 + o] = f2tf(x1g[e]);
    }
    #pragma unroll
    for (int t = 0; t < 8; t++) {
        int e = tid + t * 64;
        int i = e >> 5, v = e & 31;
        sx2[(4 * (i & 3) + (i >> 2)) * 34 + v] = f2tf(x2g[e]);
    }
    #pragma unroll
    for (int t = 0; t < 32; t++) {
        int e = tid + t * 64;
        int o = e >> 5, v = e & 31;
        int swb = (o >> 2) & 1;
        sw_[(((o * 2 + ((v >> 4) ^ swb)) * 4 + (v & 3)) << 2) + ((v >> 2) & 3)]
            = f2tf(wg[e]);
    }
    __syncthreads();

    // ---------------- t2 (pi-permuted B cols) -> registers as A-frags ------
    uint4 t2f[2][4];          // [mtl][kt] A-frag for t3
    {
        uint32_t bfr[4][4];   // x2 B-frags: [nt][s2], i = 4*s2 + j
        #pragma unroll
        for (int nt = 0; nt < 4; nt++)
            #pragma unroll
            for (int s2 = 0; s2 < 4; s2++)
                bfr[nt][s2] = sx2[(4 * j + s2) * 34 + pig + 8 * nt];

        #pragma unroll
        for (int mtl = 0; mtl < 2; mtl++) {
            float acc[4][4];
            #pragma unroll
            for (int nt = 0; nt < 4; nt++)
                #pragma unroll
                for (int q = 0; q < 4; q++) acc[nt][q] = 0.f;
            #pragma unroll
            for (int kt2 = 0; kt2 < 2; kt2++)
                #pragma unroll
                for (int nt = 0; nt < 4; nt++)
                    mma8(acc[nt], bpf[mtl][kt2], bfr[nt][2 * kt2], bfr[nt][2 * kt2 + 1]);
            // acc[nt] holds t2[16mt+g+8up][ j+4dc+8nt ] -> reorder q {0,2,1,3}
            // gives A-frag word order (up,kh): kh == dc.
            #pragma unroll
            for (int nt = 0; nt < 4; nt++) {
                t2f[mtl][nt].x = f2tf(acc[nt][0]);
                t2f[mtl][nt].y = f2tf(acc[nt][2]);
                t2f[mtl][nt].z = f2tf(acc[nt][1]);
                t2f[mtl][nt].w = f2tf(acc[nt][3]);
            }
        }
    }

    // ---------------- t1 & t3: nt outer, mtl inner (frags loaded once) -----
    const int swb = (pig >> 2) & 1;
    #pragma unroll
    for (int nt = 0; nt < 8; nt++) {
        uint32_t x1b[4];                       // x1 B-frags, i = 4*s + j
        #pragma unroll
        for (int s = 0; s < 4; s++)
            x1b[s] = sx1[(4 * j + s) * 66 + pig + 8 * nt];

        const int opi = pig + 8 * nt;
        uint4 wv4[2];
        #pragma unroll
        for (int kth = 0; kth < 2; kth++)
            wv4[kth] = ((const uint4*)sw_)[(opi * 2 + (kth ^ swb)) * 4 + j];

        #pragma unroll
        for (int mtl = 0; mtl < 2; mtl++) {
            const int mt = 2 * wid + mtl;
            float t1a[4] = {0.f, 0.f, 0.f, 0.f};
            float t3a[4] = {0.f, 0.f, 0.f, 0.f};

            mma8(t1a, apf[mtl][0], x1b[0], x1b[1]);
            mma8(t1a, apf[mtl][1], x1b[2], x1b[3]);

            mma8(t3a, t2f[mtl][0], wv4[0].x, wv4[0].y);
            mma8(t3a, t2f[mtl][1], wv4[0].z, wv4[0].w);
            mma8(t3a, t2f[mtl][2], wv4[1].x, wv4[1].y);
            mma8(t3a, t2f[mtl][3], wv4[1].z, wv4[1].w);

            // p[r=16mt+g+8up][o=j+4dc+8nt], tf32
            #pragma unroll
            for (int q = 0; q < 4; q++) {
                int up = q >> 1, dc = q & 1;
                sp[(j + 4 * dc + 8 * nt) * 68 + 16 * mt + g + 8 * up]
                    = f2tf(t1a[q] * t3a[q]);
            }
        }
    }
    __syncthreads();

    // ---------------- out = C @ p  (warp o-slice [32wid, +32)) -------------
    {
        float oacc[4][4];
        #pragma unroll
        for (int nt = 0; nt < 4; nt++)
            #pragma unroll
            for (int q = 0; q < 4; q++) oacc[nt][q] = 0.f;

        #pragma unroll
        for (int kt = 0; kt < 8; kt++) {
            uint4 cf = g_Cpack[kt * 32 + g * 4 + j];
            #pragma unroll
            for (int nt = 0; nt < 4; nt++) {
                int o = 32 * wid + 8 * nt + g;          // identity n-mapping
                uint32_t b0 = sp[o * 68 + 8 * kt + j];      // banks 4g+j, CF
                uint32_t b1 = sp[o * 68 + 8 * kt + j + 4];
                mma8(oacc[nt], cf, b0, b1);
            }
        }

        float* og = out + (size_t)b * 1024;
        #pragma unroll
        for (int nt = 0; nt < 4; nt++) {
            #pragma unroll
            for (int up = 0; up < 2; up++) {
                int c  = g + 8 * up;
                int o0 = 32 * wid + 8 * nt + 2 * j;
                *(float2*)&og[c * 64 + o0] =
                    make_float2(oacc[nt][2 * up], oacc[nt][2 * up + 1]);
            }
        }
    }
}

extern "C" void kernel_launch(void* const* d_in, const int* in_sizes, int n_in,
                              void* d_out, int out_size)
{
    const float* x1 = (const float*)d_in[0];  // (32768, 16, 64)
    const float* x2 = (const float*)d_in[1];  // (32768, 16, 32)
    const float* w  = (const float*)d_in[2];  // (32768, 64, 32)
    const float* A  = (const float*)d_in[3];  // (16, 64)
    const float* B  = (const float*)d_in[4];  // (16, 64)
    const float* C  = (const float*)d_in[5];  // (16, 64)
    float* out = (float*)d_out;               // (32768, 16, 64)

    pack_abc_kernel<<<3, 1024>>>(A, B, C);
    cp_tp_tc4<<<BATCH, 64>>>(x1, x2, w, out);
}

// round 15
// speedup vs baseline: 3.4112x; 1.0028x over previous
#include <cuda_runtime.h>
#include <cstdint>

#define BATCH  32768

// out[b,c,o] = sum_r C[c,r] * t1[b,r,o] * t3[b,r,o]
//   t1[r,o] = sum_i A[i,r] x1[i,o]     t2[r,v] = sum_i B[i,r] x2[i,v]
//   t3[r,o] = sum_v t2[r,v] w[o,v]     out[c,o]= sum_r C[c,r] (t1.*t3)[r,o]
//
// tf32 m16n8k8. One CTA = 64 threads = 2 warps per batch element; warp wid owns
// r-tiles {2wid, 2wid+1}; pi-trick keeps t2 in registers as t3 A-fragments.
//
// R15: XOR-swizzled smem layouts -> every STS and LDS in the kernel is
// bank-conflict-free; p loads are LDS.64 (rho-permuted r makes pairs adjacent);
// staging uses LDG.128 + STS.128 where the layout allows.

__device__ __forceinline__ uint32_t f2tf(float x) {
    uint32_t r;
    asm("cvt.rna.tf32.f32 %0, %1;" : "=r"(r) : "f"(x));
    return r;
}

__device__ __forceinline__ void mma8(float* c, uint4 a, uint32_t b0, uint32_t b1) {
    asm volatile(
        "mma.sync.aligned.m16n8k8.row.col.f32.tf32.tf32.f32 "
        "{%0,%1,%2,%3}, {%4,%5,%6,%7}, {%8,%9}, {%0,%1,%2,%3};"
        : "+f"(c[0]), "+f"(c[1]), "+f"(c[2]), "+f"(c[3])
        : "r"(a.x), "r"(a.y), "r"(a.z), "r"(a.w), "r"(b0), "r"(b1));
}

// Prepacked A-operand fragments (uint4 per thread-slot).
// A/B slot: [mt*2+kt][g][j], words w=(up=w&1,kh=w>>1) -> elem [16mt+g+8up][8kt+j+4kh]
// C   slot: [kt(0..7)][g][j]                          -> elem C[g+8up][8kt+j+4kh]
__device__ uint4 g_Apack[256];
__device__ uint4 g_Bpack[256];
__device__ uint4 g_Cpack[256];

__global__ void pack_abc_kernel(const float* __restrict__ A,
                                const float* __restrict__ B,
                                const float* __restrict__ C)
{
    int s = blockIdx.x * blockDim.x + threadIdx.x;   // 0..3071
    if (s >= 3072) return;
    int w  = s & 3;
    int j  = (s >> 2) & 3;
    int g  = (s >> 4) & 7;
    int kf = (s >> 7) & 7;
    int m  = s >> 10;                                // 0=A 1=B 2=C
    int up = w & 1, kh = w >> 1;
    float v;
    uint32_t* dst;
    if (m < 2) {
        int i = 8 * (kf & 1) + j + 4 * kh;
        int r = 16 * (kf >> 1) + g + 8 * up;
        v = (m == 0 ? A : B)[i * 64 + r];
        dst = (m == 0) ? (uint32_t*)g_Apack : (uint32_t*)g_Bpack;
    } else {
        int c = g + 8 * up;
        int r = 8 * kf + j + 4 * kh;
        v = C[c * 64 + r];
        dst = (uint32_t*)g_Cpack;
    }
    dst[s & 1023] = f2tf(v);
}

__global__ __launch_bounds__(64, 7)
void cp_tp_tc5(const float* __restrict__ x1,
               const float* __restrict__ x2,
               const float* __restrict__ w,
               float* __restrict__ out)
{
    const int b    = blockIdx.x;
    const int tid  = threadIdx.x;          // 0..63
    const int lane = tid & 31;
    const int wid  = tid >> 5;             // 0..1
    const int g    = lane >> 2;            // 0..7
    const int j    = lane & 3;             // 0..3
    const int pig  = (g >> 1) + 4 * (g & 1);   // pi(g)
    const int rhog = 2 * (g & 3) + (g >> 2);   // rho(g)

    // XOR-swizzled layouts (word addresses):
    //  sx1: word = row*64 + (o ^ 8*(row>>2 & 3)),  row(i) = 4(i&3)+(i>>2)
    //  sx2: word = row*32 + (v ^ 8*(row>>2 & 3))
    //  sw_: word = (o*2 + ((v>>4)^((o>>2)&1)))*16 + 4*((v&3)^(o&3)) + ((v>>2)&3)
    //  sp : word = o*64 + (r' ^ 8*(o&3)),  r' = (r&~7) | rho(r&7)
    __shared__ uint32_t sx1[1024];
    __shared__ uint32_t sx2[512];
    __shared__ uint32_t sw_[2048];
    __shared__ uint32_t sp [4096];

    const float* x1g = x1 + (size_t)b * 1024;
    const float* x2g = x2 + (size_t)b * 512;
    const float* wg  = w  + (size_t)b * 2048;

    // prefetch batch-invariant fragments (overlap with staging)
    uint4 apf[2][2], bpf[2][2];
    #pragma unroll
    for (int mtl = 0; mtl < 2; mtl++)
        #pragma unroll
        for (int kt = 0; kt < 2; kt++) {
            int mt = 2 * wid + mtl;
            apf[mtl][kt] = g_Apack[(mt * 2 + kt) * 32 + g * 4 + j];
            bpf[mtl][kt] = g_Bpack[(mt * 2 + kt) * 32 + g * 4 + j];
        }

    // ---------------- stage x1/x2/w: LDG.128 + CF stores -------------------
    #pragma unroll
    for (int t = 0; t < 4; t++) {           // x1: 256 quads
        int q  = tid + t * 64;
        int i  = q >> 4, oq = q & 15;
        float4 v4 = ((const float4*)x1g)[q];
        uint4  u4 = make_uint4(f2tf(v4.x), f2tf(v4.y), f2tf(v4.z), f2tf(v4.w));
        int row = 4 * (i & 3) + (i >> 2);
        *(uint4*)&sx1[row * 64 + ((4 * oq) ^ (8 * (i & 3)))] = u4;   // STS.128 CF
    }
    #pragma unroll
    for (int t = 0; t < 2; t++) {           // x2: 128 quads
        int q  = tid + t * 64;
        int i  = q >> 3, vq = q & 7;
        float4 v4 = ((const float4*)x2g)[q];
        uint4  u4 = make_uint4(f2tf(v4.x), f2tf(v4.y), f2tf(v4.z), f2tf(v4.w));
        int row = 4 * (i & 3) + (i >> 2);
        *(uint4*)&sx2[row * 32 + ((4 * vq) ^ (8 * (i & 3)))] = u4;   // STS.128 CF
    }
    #pragma unroll
    for (int t = 0; t < 8; t++) {           // w: 512 quads, scatter STS.32 (CF)
        int q = tid + t * 64;
        int o = q >> 3, a = q & 7;          // v = 4a + b
        float4 v4 = ((const float4*)wg)[q];
        int swb  = (o >> 2) & 1;
        int base = (o * 2 + ((a >> 2) ^ swb)) * 16 + (a & 3);
        int om3  = o & 3;
        sw_[base + 4 * (0 ^ om3)] = f2tf(v4.x);
        sw_[base + 4 * (1 ^ om3)] = f2tf(v4.y);
        sw_[base + 4 * (2 ^ om3)] = f2tf(v4.z);
        sw_[base + 4 * (3 ^ om3)] = f2tf(v4.w);
    }
    __syncthreads();

    // ---------------- t2 (pi-permuted B cols) -> registers as A-frags ------
    uint4 t2f[2][4];          // [mtl][kt] A-frag for t3
    {
        uint32_t bfr[4][4];   // x2 B-frags: [nt][s2], i = 4*s2 + j ... row = 4j+s2
        #pragma unroll
        for (int nt = 0; nt < 4; nt++)
            #pragma unroll
            for (int s2 = 0; s2 < 4; s2++)
                bfr[nt][s2] = sx2[(4 * j + s2) * 32 + ((pig + 8 * nt) ^ (8 * j))];

        #pragma unroll
        for (int mtl = 0; mtl < 2; mtl++) {
            float acc[4][4];
            #pragma unroll
            for (int nt = 0; nt < 4; nt++)
                #pragma unroll
                for (int q = 0; q < 4; q++) acc[nt][q] = 0.f;
            #pragma unroll
            for (int kt2 = 0; kt2 < 2; kt2++)
                #pragma unroll
                for (int nt = 0; nt < 4; nt++)
                    mma8(acc[nt], bpf[mtl][kt2], bfr[nt][2 * kt2], bfr[nt][2 * kt2 + 1]);
            // reorder q {0,2,1,3}: accumulator -> A-frag word order
            #pragma unroll
            for (int nt = 0; nt < 4; nt++) {
                t2f[mtl][nt].x = f2tf(acc[nt][0]);
                t2f[mtl][nt].y = f2tf(acc[nt][2]);
                t2f[mtl][nt].z = f2tf(acc[nt][1]);
                t2f[mtl][nt].w = f2tf(acc[nt][3]);
            }
        }
    }

    // ---------------- t1 & t3: nt outer, mtl inner -------------------------
    const int swb_l = (pig >> 2) & 1;
    const int pm3   = pig & 3;
    #pragma unroll
    for (int nt = 0; nt < 8; nt++) {
        uint32_t x1b[4];                       // x1 B-frags, row = 4j+s
        #pragma unroll
        for (int s = 0; s < 4; s++)
            x1b[s] = sx1[(4 * j + s) * 64 + ((pig + 8 * nt) ^ (8 * j))];

        const int opi = pig + 8 * nt;
        uint4 wv4[2];
        #pragma unroll
        for (int kth = 0; kth < 2; kth++)
            wv4[kth] = ((const uint4*)sw_)[(opi * 2 + (kth ^ swb_l)) * 4 + (j ^ pm3)];

        #pragma unroll
        for (int mtl = 0; mtl < 2; mtl++) {
            const int mt = 2 * wid + mtl;
            float t1a[4] = {0.f, 0.f, 0.f, 0.f};
            float t3a[4] = {0.f, 0.f, 0.f, 0.f};

            mma8(t1a, apf[mtl][0], x1b[0], x1b[1]);
            mma8(t1a, apf[mtl][1], x1b[2], x1b[3]);

            mma8(t3a, t2f[mtl][0], wv4[0].x, wv4[0].y);
            mma8(t3a, t2f[mtl][1], wv4[0].z, wv4[0].w);
            mma8(t3a, t2f[mtl][2], wv4[1].x, wv4[1].y);
            mma8(t3a, t2f[mtl][3], wv4[1].z, wv4[1].w);

            // p[r=16mt+g+8up][o=j+4dc+8nt]: CF STS.32 (r' = 16mt+8up+rho(g))
            #pragma unroll
            for (int q = 0; q < 4; q++) {
                int up = q >> 1, dc = q & 1;
                int o  = j + 4 * dc + 8 * nt;
                int rp = 16 * mt + 8 * up + rhog;
                sp[o * 64 + (rp ^ (8 * j))] = f2tf(t1a[q] * t3a[q]);
            }
        }
    }
    __syncthreads();

    // ---------------- out = C @ p  (warp o-slice [32wid, +32)) -------------
    {
        float oacc[4][4];
        #pragma unroll
        for (int nt = 0; nt < 4; nt++)
            #pragma unroll
            for (int q = 0; q < 4; q++) oacc[nt][q] = 0.f;

        const int gm3 = g & 3;
        #pragma unroll
        for (int kt = 0; kt < 8; kt++) {
            uint4 cf = g_Cpack[kt * 32 + g * 4 + j];
            #pragma unroll
            for (int nt = 0; nt < 4; nt++) {
                int o = 32 * wid + 8 * nt + g;
                // LDS.64: words r' = {8kt+2j, 8kt+2j+1} -> p[8kt+j], p[8kt+j+4]
                uint2 pp = *(const uint2*)&sp[o * 64 + (((8 * kt + 2 * j) ^ (8 * gm3)))];
                mma8(oacc[nt], cf, pp.x, pp.y);
            }
        }

        float* og = out + (size_t)b * 1024;
        #pragma unroll
        for (int nt = 0; nt < 4; nt++) {
            #pragma unroll
            for (int up = 0; up < 2; up++) {
                int c  = g + 8 * up;
                int o0 = 32 * wid + 8 * nt + 2 * j;
                *(float2*)&og[c * 64 + o0] =
                    make_float2(oacc[nt][2 * up], oacc[nt][2 * up + 1]);
            }
        }
    }
}

extern "C" void kernel_launch(void* const* d_in, const int* in_sizes, int n_in,
                              void* d_out, int out_size)
{
    const float* x1 = (const float*)d_in[0];  // (32768, 16, 64)
    const float* x2 = (const float*)d_in[1];  // (32768, 16, 32)
    const float* w  = (const float*)d_in[2];  // (32768, 64, 32)
    const float* A  = (const float*)d_in[3];  // (16, 64)
    const float* B  = (const float*)d_in[4];  // (16, 64)
    const float* C  = (const float*)d_in[5];  // (16, 64)
    float* out = (float*)d_out;               // (32768, 16, 64)

    pack_abc_kernel<<<3, 1024>>>(A, B, C);
    cp_tp_tc5<<<BATCH, 64>>>(x1, x2, w, out);
}

// round 17
// speedup vs baseline: 3.8060x; 1.1157x over previous
#include <cuda_runtime.h>
#include <cuda_fp16.h>
#include <cstdint>

#define BATCH  32768

// out[b,c,o] = sum_r C[c,r] * t1[b,r,o] * t3[b,r,o]
//   t1[r,o] = sum_i A[i,r] x1[i,o]     t2[r,v] = sum_i B[i,r] x2[i,v]
//   t3[r,o] = sum_v t2[r,v] w[o,v]     out[c,o]= sum_r C[c,r] (t1.*t3)[r,o]
//
// tf32 m16n8k8 for t1/t2/t3; fp16 m16n8k16 for the final out GEMM.
// One CTA = 64 threads = 2 warps per element; warp wid owns r-tiles {2wid,2wid+1};
// pi-trick keeps t2 in registers as t3 A-fragments.
//
// R16: final GEMM in fp16 -> p-exchange buffer halves to 8 KB (smem 22 KB,
// 9 CTAs/SM vs 7), p stores become packed f16x2 (half the cvt+STS), out mma
// count halves. k-mapping r'' = 16mt + 2g + up pairs each thread's (up0,up1)
// into one f16x2 word; C is pre-packed with the same permutation.

__device__ __forceinline__ uint32_t f2tf(float x) {
    uint32_t r;
    asm("cvt.rna.tf32.f32 %0, %1;" : "=r"(r) : "f"(x));
    return r;
}

__device__ __forceinline__ void mma8(float* c, uint4 a, uint32_t b0, uint32_t b1) {
    asm volatile(
        "mma.sync.aligned.m16n8k8.row.col.f32.tf32.tf32.f32 "
        "{%0,%1,%2,%3}, {%4,%5,%6,%7}, {%8,%9}, {%0,%1,%2,%3};"
        : "+f"(c[0]), "+f"(c[1]), "+f"(c[2]), "+f"(c[3])
        : "r"(a.x), "r"(a.y), "r"(a.z), "r"(a.w), "r"(b0), "r"(b1));
}

__device__ __forceinline__ void mma16(float* c, uint4 a, uint32_t b0, uint32_t b1) {
    asm volatile(
        "mma.sync.aligned.m16n8k16.row.col.f32.f16.f16.f32 "
        "{%0,%1,%2,%3}, {%4,%5,%6,%7}, {%8,%9}, {%0,%1,%2,%3};"
        : "+f"(c[0]), "+f"(c[1]), "+f"(c[2]), "+f"(c[3])
        : "r"(a.x), "r"(a.y), "r"(a.z), "r"(a.w), "r"(b0), "r"(b1));
}

// Prepacked fragments.
// A/B (tf32) slot [mt*2+kt][g][j], words w=(up=w&1,kh=w>>1):
//   elem [16mt+g+8up][8kt+j+4kh]
// C (fp16, m16n8k16 A-frag with k-permutation r'' = 16kt2 + 2g_p + up):
//   slot [kt2][g][j], word w: row = g+8*(w&1), colbase = 16kt2 + j + 4*(w>>1)
//   f16x2 = { C[row][colbase] (lo, k-even), C[row][colbase+8] (hi, k-odd) }
__device__ uint4 g_Apack[256];
__device__ uint4 g_Bpack[256];
__device__ uint4 g_Cpack16[128];

__global__ void pack_abc_kernel(const float* __restrict__ A,
                                const float* __restrict__ B,
                                const float* __restrict__ C)
{
    int s = blockIdx.x * blockDim.x + threadIdx.x;   // 0..3071
    if (s >= 3072) return;
    int m = s >> 10;                                 // 0=A 1=B 2=C
    if (m < 2) {
        int w  = s & 3;
        int j  = (s >> 2) & 3;
        int g  = (s >> 4) & 7;
        int kf = (s >> 7) & 7;
        int up = w & 1, kh = w >> 1;
        int i = 8 * (kf & 1) + j + 4 * kh;
        int r = 16 * (kf >> 1) + g + 8 * up;
        float v = (m == 0 ? A : B)[i * 64 + r];
        uint32_t* dst = (m == 0) ? (uint32_t*)g_Apack : (uint32_t*)g_Bpack;
        dst[s & 1023] = f2tf(v);
    } else {
        int cidx = s & 1023;
        if (cidx >= 512) return;
        int w   = cidx & 3;
        int jj  = (cidx >> 2) & 3;
        int gg  = (cidx >> 4) & 7;
        int kt2 = cidx >> 7;
        int row = gg + 8 * (w & 1);
        int col = 16 * kt2 + jj + 4 * (w >> 1);
        __half2 h = __floats2half2_rn(C[row * 64 + col], C[row * 64 + col + 8]);
        ((uint32_t*)g_Cpack16)[cidx] = *(uint32_t*)&h;
    }
}

__global__ __launch_bounds__(64, 9)
void cp_tp_tc6(const float* __restrict__ x1,
               const float* __restrict__ x2,
               const float* __restrict__ w,
               float* __restrict__ out)
{
    const int b    = blockIdx.x;
    const int tid  = threadIdx.x;          // 0..63
    const int lane = tid & 31;
    const int wid  = tid >> 5;             // 0..1
    const int g    = lane >> 2;            // 0..7
    const int j    = lane & 3;             // 0..3
    const int pig  = (g >> 1) + 4 * (g & 1);   // pi(g)

    // XOR-swizzled layouts (word addresses):
    //  sx1: word = row*64 + (o ^ 8*(row>>2 & 3)),  row(i) = 4(i&3)+(i>>2)
    //  sx2: word = row*32 + (v ^ 8*(row>>2 & 3))
    //  sw_: word = (o*2 + ((v>>4)^((o>>2)&1)))*16 + 4*((v&3)^(o&3)) + ((v>>2)&3)
    //  sp16: fp16 p; word(o, mt, g_p) = o*32 + ((8mt+g_p) ^ 4*(o&7)),
    //        word holds halves (up0 lo, up1 hi) of r = 16mt + 8up + g_p
    __shared__ uint32_t sx1[1024];
    __shared__ uint32_t sx2[512];
    __shared__ uint32_t sw_[2048];
    __shared__ uint32_t sp16[2048];

    const float* x1g = x1 + (size_t)b * 1024;
    const float* x2g = x2 + (size_t)b * 512;
    const float* wg  = w  + (size_t)b * 2048;

    // prefetch batch-invariant fragments (overlap with staging)
    uint4 apf[2][2], bpf[2][2];
    #pragma unroll
    for (int mtl = 0; mtl < 2; mtl++)
        #pragma unroll
        for (int kt = 0; kt < 2; kt++) {
            int mt = 2 * wid + mtl;
            apf[mtl][kt] = g_Apack[(mt * 2 + kt) * 32 + g * 4 + j];
            bpf[mtl][kt] = g_Bpack[(mt * 2 + kt) * 32 + g * 4 + j];
        }

    // ---------------- stage x1/x2/w: LDG.128 + CF stores -------------------
    #pragma unroll
    for (int t = 0; t < 4; t++) {           // x1: 256 quads
        int q  = tid + t * 64;
        int i  = q >> 4, oq = q & 15;
        float4 v4 = ((const float4*)x1g)[q];
        uint4  u4 = make_uint4(f2tf(v4.x), f2tf(v4.y), f2tf(v4.z), f2tf(v4.w));
        int row = 4 * (i & 3) + (i >> 2);
        *(uint4*)&sx1[row * 64 + ((4 * oq) ^ (8 * (i & 3)))] = u4;   // STS.128 CF
    }
    #pragma unroll
    for (int t = 0; t < 2; t++) {           // x2: 128 quads
        int q  = tid + t * 64;
        int i  = q >> 3, vq = q & 7;
        float4 v4 = ((const float4*)x2g)[q];
        uint4  u4 = make_uint4(f2tf(v4.x), f2tf(v4.y), f2tf(v4.z), f2tf(v4.w));
        int row = 4 * (i & 3) + (i >> 2);
        *(uint4*)&sx2[row * 32 + ((4 * vq) ^ (8 * (i & 3)))] = u4;   // STS.128 CF
    }
    #pragma unroll
    for (int t = 0; t < 8; t++) {           // w: 512 quads, scatter STS.32 (CF)
        int q = tid + t * 64;
        int o = q >> 3, a = q & 7;          // v = 4a + b
        float4 v4 = ((const float4*)wg)[q];
        int swb  = (o >> 2) & 1;
        int base = (o * 2 + ((a >> 2) ^ swb)) * 16 + (a & 3);
        int om3  = o & 3;
        sw_[base + 4 * (0 ^ om3)] = f2tf(v4.x);
        sw_[base + 4 * (1 ^ om3)] = f2tf(v4.y);
        sw_[base + 4 * (2 ^ om3)] = f2tf(v4.z);
        sw_[base + 4 * (3 ^ om3)] = f2tf(v4.w);
    }
    __syncthreads();

    // ---------------- t2 (pi-permuted B cols) -> registers as A-frags ------
    uint4 t2f[2][4];          // [mtl][kt] A-frag for t3
    {
        uint32_t bfr[4][4];   // x2 B-frags: [nt][s2], row = 4j+s2
        #pragma unroll
        for (int nt = 0; nt < 4; nt++)
            #pragma unroll
            for (int s2 = 0; s2 < 4; s2++)
                bfr[nt][s2] = sx2[(4 * j + s2) * 32 + ((pig + 8 * nt) ^ (8 * j))];

        #pragma unroll
        for (int mtl = 0; mtl < 2; mtl++) {
            float acc[4][4];
            #pragma unroll
            for (int nt = 0; nt < 4; nt++)
                #pragma unroll
                for (int q = 0; q < 4; q++) acc[nt][q] = 0.f;
            #pragma unroll
            for (int kt2 = 0; kt2 < 2; kt2++)
                #pragma unroll
                for (int nt = 0; nt < 4; nt++)
                    mma8(acc[nt], bpf[mtl][kt2], bfr[nt][2 * kt2], bfr[nt][2 * kt2 + 1]);
            // reorder q {0,2,1,3}: accumulator -> A-frag word order
            #pragma unroll
            for (int nt = 0; nt < 4; nt++) {
                t2f[mtl][nt].x = f2tf(acc[nt][0]);
                t2f[mtl][nt].y = f2tf(acc[nt][2]);
                t2f[mtl][nt].z = f2tf(acc[nt][1]);
                t2f[mtl][nt].w = f2tf(acc[nt][3]);
            }
        }
    }

    // ---------------- t1 & t3: nt outer, mtl inner; p -> fp16 smem ---------
    const int swb_l = (pig >> 2) & 1;
    const int pm3   = pig & 3;
    #pragma unroll
    for (int nt = 0; nt < 8; nt++) {
        uint32_t x1b[4];                       // x1 B-frags, row = 4j+s
        #pragma unroll
        for (int s = 0; s < 4; s++)
            x1b[s] = sx1[(4 * j + s) * 64 + ((pig + 8 * nt) ^ (8 * j))];

        const int opi = pig + 8 * nt;
        uint4 wv4[2];
        #pragma unroll
        for (int kth = 0; kth < 2; kth++)
            wv4[kth] = ((const uint4*)sw_)[(opi * 2 + (kth ^ swb_l)) * 4 + (j ^ pm3)];

        #pragma unroll
        for (int mtl = 0; mtl < 2; mtl++) {
            const int mt = 2 * wid + mtl;
            float t1a[4] = {0.f, 0.f, 0.f, 0.f};
            float t3a[4] = {0.f, 0.f, 0.f, 0.f};

            mma8(t1a, apf[mtl][0], x1b[0], x1b[1]);
            mma8(t1a, apf[mtl][1], x1b[2], x1b[3]);

            mma8(t3a, t2f[mtl][0], wv4[0].x, wv4[0].y);
            mma8(t3a, t2f[mtl][1], wv4[0].z, wv4[0].w);
            mma8(t3a, t2f[mtl][2], wv4[1].x, wv4[1].y);
            mma8(t3a, t2f[mtl][3], wv4[1].z, wv4[1].w);

            // p[r=16mt+8up+g][o=j+4dc+8nt] -> f16x2 (up0 lo, up1 hi), one STS.32
            #pragma unroll
            for (int dc = 0; dc < 2; dc++) {
                float v0 = t1a[dc]     * t3a[dc];        // up = 0
                float v1 = t1a[dc + 2] * t3a[dc + 2];    // up = 1
                __half2 h = __floats2half2_rn(v0, v1);
                int o = j + 4 * dc + 8 * nt;             // o & 7 = j + 4dc
                sp16[o * 32 + ((8 * mt + g) ^ (4 * (j + 4 * dc)))] = *(uint32_t*)&h;
            }
        }
    }
    __syncthreads();

    // ---------------- out = C @ p  fp16 m16n8k16 (o-slice [32wid,+32)) -----
    {
        float oacc[4][4];
        #pragma unroll
        for (int nt = 0; nt < 4; nt++)
            #pragma unroll
            for (int q = 0; q < 4; q++) oacc[nt][q] = 0.f;

        #pragma unroll
        for (int kt2 = 0; kt2 < 4; kt2++) {
            uint4 cf = g_Cpack16[kt2 * 32 + g * 4 + j];
            #pragma unroll
            for (int nt = 0; nt < 4; nt++) {
                int o = 32 * wid + 8 * nt + g;           // o & 7 = g
                uint32_t b0 = sp16[o * 32 + ((8 * kt2 + j)     ^ (4 * g))];  // CF
                uint32_t b1 = sp16[o * 32 + ((8 * kt2 + j + 4) ^ (4 * g))];  // CF
                mma16(oacc[nt], cf, b0, b1);
            }
        }

        float* og = out + (size_t)b * 1024;
        #pragma unroll
        for (int nt = 0; nt < 4; nt++) {
            #pragma unroll
            for (int up = 0; up < 2; up++) {
                int c  = g + 8 * up;
                int o0 = 32 * wid + 8 * nt + 2 * j;
                *(float2*)&og[c * 64 + o0] =
                    make_float2(oacc[nt][2 * up], oacc[nt][2 * up + 1]);
            }
        }
    }
}

extern "C" void kernel_launch(void* const* d_in, const int* in_sizes, int n_in,
                              void* d_out, int out_size)
{
    const float* x1 = (const float*)d_in[0];  // (32768, 16, 64)
    const float* x2 = (const float*)d_in[1];  // (32768, 16, 32)
    const float* w  = (const float*)d_in[2];  // (32768, 64, 32)
    const float* A  = (const float*)d_in[3];  // (16, 64)
    const float* B  = (const float*)d_in[4];  // (16, 64)
    const float* C  = (const float*)d_in[5];  // (16, 64)
    float* out = (float*)d_out;               // (32768, 16, 64)

    pack_abc_kernel<<<3, 1024>>>(A, B, C);
    cp_tp_tc6<<<BATCH, 64>>>(x1, x2, w, out);
}